// round 13
// baseline (speedup 1.0000x reference)
#include <cuda_runtime.h>
#include <cuda_bf16.h>
#include <cstdint>

#define B 8
#define D 256
#define HW (128 * 128)
#define C 80
#define NPIX (B * HW)
#define RANGE_EXTENDER 10.0f
#define EPS 1e-8f

#define KC 64                 // K per chunk
#define NT (D / KC)           // 4 chunks
#define PXT 128               // pixels per CTA (= M)
#define NTHREADS 256          // 8 warps: 4 px-groups x 2 ch-groups

// smem map (dynamic)
#define S_W   0               // 2 x 20480 (wh 10240 + wl 10240)
#define S_XS  40960           // 2 x (xh 16KB + xl 16KB)
#define S_NP  106496          // norm partials 2*128*4
#define S_NI  107520          // inv norms 128*4
#define S_TOTAL 108032

// Pre-split weight image, 16B-swizzled: [chunk t][hl][c][128B]
__device__ __align__(16) unsigned char g_wimg[NT * 2 * C * 128];

// ---------------------------------------------------------------------------
// helpers
// ---------------------------------------------------------------------------
__device__ __forceinline__ uint32_t smem_u32(const void* p) {
    return (uint32_t)__cvta_generic_to_shared(p);
}
__device__ __forceinline__ void cp_async16(uint32_t s, const void* g) {
    asm volatile("cp.async.cg.shared.global [%0], [%1], 16;" :: "r"(s), "l"(g) : "memory");
}
__device__ __forceinline__ void cp_commit() {
    asm volatile("cp.async.commit_group;" ::: "memory");
}
template <int N> __device__ __forceinline__ void cp_wait() {
    asm volatile("cp.async.wait_group %0;" :: "n"(N) : "memory");
}
__device__ __forceinline__ uint32_t cvt_bf16x2(float lo, float hi) {
    uint32_t r;
    asm("cvt.rn.bf16x2.f32 %0, %1, %2;" : "=r"(r) : "f"(hi), "f"(lo));
    return r;
}
__device__ __forceinline__ void ldsm_x4(uint32_t* r, uint32_t addr) {
    asm volatile("ldmatrix.sync.aligned.m8n8.x4.shared.b16 {%0,%1,%2,%3}, [%4];"
                 : "=r"(r[0]), "=r"(r[1]), "=r"(r[2]), "=r"(r[3]) : "r"(addr));
}
__device__ __forceinline__ void ldsm_x2(uint32_t* r, uint32_t addr) {
    asm volatile("ldmatrix.sync.aligned.m8n8.x2.shared.b16 {%0,%1}, [%2];"
                 : "=r"(r[0]), "=r"(r[1]) : "r"(addr));
}
__device__ __forceinline__ void mma_bf16(float* d, const uint32_t* a,
                                         uint32_t b0, uint32_t b1) {
    asm volatile(
        "mma.sync.aligned.m16n8k16.row.col.f32.bf16.bf16.f32 "
        "{%0,%1,%2,%3}, {%4,%5,%6,%7}, {%8,%9}, {%0,%1,%2,%3};"
        : "+f"(d[0]), "+f"(d[1]), "+f"(d[2]), "+f"(d[3])
        : "r"(a[0]), "r"(a[1]), "r"(a[2]), "r"(a[3]), "r"(b0), "r"(b1));
}

// ---------------------------------------------------------------------------
// Kernel 1: normalize+scale weights; bf16 hi/lo split; 16B-swizzled image
// rows of 128B (8 chunks), 3-bit XOR swizzle
// ---------------------------------------------------------------------------
__global__ void prep_weights_kernel(const float* __restrict__ w,
                                    const float* __restrict__ asf) {
    int c = blockIdx.x;
    int d = threadIdx.x;
    float v = w[c * D + d];

    __shared__ float red[D];
    red[d] = v * v;
    __syncthreads();
    #pragma unroll
    for (int s = D / 2; s > 0; s >>= 1) {
        if (d < s) red[d] += red[d + s];
        __syncthreads();
    }
    float scale = asf[c] * RANGE_EXTENDER / fmaxf(sqrtf(red[0]), EPS);
    float wn = v * scale;

    __nv_bfloat16 h = __float2bfloat16(wn);
    __nv_bfloat16 l = __float2bfloat16(wn - __bfloat162float(h));

    int t  = d >> 6;                  // chunk (KC=64)
    int kl = d & 63;
    int kp = kl >> 1;
    int ck = kp >> 2;                 // 16B chunk within 128B row (0..7)
    int word = kp & 3;
    int inner = ((ck ^ ((c >> 1) & 7)) << 4) + (word << 2) + (kl & 1) * 2;

    size_t hb = (size_t)t * 20480 + (size_t)c * 128 + inner;
    size_t lb = hb + 10240;
    *reinterpret_cast<__nv_bfloat16*>(g_wimg + hb) = h;
    *reinterpret_cast<__nv_bfloat16*>(g_wimg + lb) = l;
}

// ---------------------------------------------------------------------------
// Kernel 2: bf16 mma.sync GEMM, 3-term split, KC=64 chunks, convert woven
// between s-steps, one barrier per chunk.
// ---------------------------------------------------------------------------
__global__ __launch_bounds__(NTHREADS, 2)
void coshead_main_kernel(const float* __restrict__ x, float* __restrict__ out) {
    extern __shared__ char smem[];
    const uint32_t sb = smem_u32(smem);

    const int tid  = threadIdx.x;
    const int lane = tid & 31;
    const int wid  = tid >> 5;
    const int pxbase = (wid & 3) * 32;
    const int chbase = (wid >> 2) * 40;
    const int r = lane >> 2;
    const int q = lane & 3;
    const int mat = lane >> 3, rowi = lane & 7;

    const int tile    = blockIdx.x;
    const int b       = (tile * PXT) >> 14;
    const int hw_base = (tile * PXT) & (HW - 1);
    const float* xg = x + ((size_t)b * D) * HW + hw_base;

    const int cpx  = tid & 127;       // conversion pixel
    const int half = tid >> 7;        // conversion k-half of chunk (32 k each)
    float n2 = 0.0f;

    auto stage_w = [&](int t, int buf) {
        const unsigned char* ws = g_wimg + (size_t)t * 20480;
        uint32_t wd = sb + S_W + buf * 20480;
        #pragma unroll
        for (int i = tid, j = 0; j < 5; j++, i += NTHREADS)
            cp_async16(wd + i * 16, ws + i * 16);
        cp_commit();
    };

    // load 16 x values for (chunk t, this thread's half, batch) into regs
    auto prefetch = [&](int t, int batch, float* xv) {
        const float* xr = xg + (size_t)(t * KC + half * 32 + batch * 16) * HW + cpx;
        #pragma unroll
        for (int j = 0; j < 16; j++) xv[j] = xr[(size_t)j * HW];
    };

    // convert a 16-value batch into XS[buf]
    auto convert = [&](const float* xv, int buf, int batch) {
        char* xh = smem + S_XS + buf * 32768;
        char* xl = xh + 16384;
        int ck0 = (half * 32 + batch * 16) >> 3;   // first 16B chunk (2 per batch)
        #pragma unroll
        for (int c2 = 0; c2 < 2; c2++) {
            uint32_t wh[4], wl[4];
            #pragma unroll
            for (int i = 0; i < 4; i++) {
                float v0 = xv[c2 * 8 + i * 2];
                float v1 = xv[c2 * 8 + i * 2 + 1];
                n2 = fmaf(v0, v0, n2);
                n2 = fmaf(v1, v1, n2);
                __nv_bfloat16 h0 = __float2bfloat16(v0);
                __nv_bfloat16 h1 = __float2bfloat16(v1);
                float l0 = v0 - __bfloat162float(h0);
                float l1 = v1 - __bfloat162float(h1);
                wh[i] = ((uint32_t)__bfloat16_as_ushort(h1) << 16)
                      | __bfloat16_as_ushort(h0);
                wl[i] = cvt_bf16x2(l0, l1);
            }
            int ck = ck0 + c2;
            int addr = cpx * 128 + ((ck ^ ((cpx >> 1) & 7)) << 4);
            *reinterpret_cast<uint4*>(xh + addr) = make_uint4(wh[0], wh[1], wh[2], wh[3]);
            *reinterpret_cast<uint4*>(xl + addr) = make_uint4(wl[0], wl[1], wl[2], wl[3]);
        }
    };

    float acc[2][5][4];
    #pragma unroll
    for (int m = 0; m < 2; m++)
        #pragma unroll
        for (int n = 0; n < 5; n++)
            #pragma unroll
            for (int k = 0; k < 4; k++) acc[m][n][k] = 0.0f;

    // one k16-step of MMAs (s in 0..3)
    auto mma_step = [&](int s, uint32_t xhb, uint32_t whb) {
        uint32_t ah[2][4], al_[2][4];
        #pragma unroll
        for (int m = 0; m < 2; m++) {
            int px = pxbase + m * 16 + ((mat & 1) << 3) + rowi;
            int ck = 2 * s + (mat >> 1);
            uint32_t a = xhb + px * 128 + ((ck ^ ((px >> 1) & 7)) << 4);
            ldsm_x4(ah[m], a);
            ldsm_x4(al_[m], a + 16384);
        }
        uint32_t bh[5][2], bl[5][2];
        #pragma unroll
        for (int u = 0; u < 2; u++) {
            int cc = chbase + u * 16 + ((mat >> 1) << 3) + rowi;
            int ck = 2 * s + (mat & 1);
            uint32_t a = whb + cc * 128 + ((ck ^ ((cc >> 1) & 7)) << 4);
            uint32_t rr[4];
            ldsm_x4(rr, a);
            bh[2 * u][0] = rr[0]; bh[2 * u][1] = rr[1];
            bh[2 * u + 1][0] = rr[2]; bh[2 * u + 1][1] = rr[3];
            ldsm_x4(rr, a + 10240);
            bl[2 * u][0] = rr[0]; bl[2 * u][1] = rr[1];
            bl[2 * u + 1][0] = rr[2]; bl[2 * u + 1][1] = rr[3];
        }
        {
            int cc = chbase + 32 + rowi;
            int ck = 2 * s + (mat & 1);
            uint32_t a = whb + cc * 128 + ((ck ^ ((cc >> 1) & 7)) << 4);
            uint32_t rr[2];
            ldsm_x2(rr, a);
            bh[4][0] = rr[0]; bh[4][1] = rr[1];
            ldsm_x2(rr, a + 10240);
            bl[4][0] = rr[0]; bl[4][1] = rr[1];
        }
        #pragma unroll
        for (int n = 0; n < 5; n++)
            #pragma unroll
            for (int m = 0; m < 2; m++) {
                mma_bf16(acc[m][n], ah[m],  bh[n][0], bh[n][1]);
                mma_bf16(acc[m][n], al_[m], bh[n][0], bh[n][1]);
                mma_bf16(acc[m][n], ah[m],  bl[n][0], bl[n][1]);
            }
    };

    // ---- prologue ----
    stage_w(0, 0);
    {
        float xv[16];
        prefetch(0, 0, xv);
        convert(xv, 0, 0);
        prefetch(0, 1, xv);
        convert(xv, 0, 1);
    }
    cp_wait<0>();
    __syncthreads();

    for (int t = 0; t < NT; t++) {
        const int buf = t & 1;
        if (t + 1 < NT) { stage_w(t + 1, buf ^ 1); cp_wait<1>(); }
        else           { cp_wait<0>(); }
        if (t > 0) __syncthreads();   // XS[buf] converted; W[buf] ready

        const uint32_t xhb = sb + S_XS + buf * 32768;
        const uint32_t whb = sb + S_W + buf * 20480;

        float xv[16];
        if (t + 1 < NT) prefetch(t + 1, 0, xv);
        mma_step(0, xhb, whb);
        mma_step(1, xhb, whb);
        if (t + 1 < NT) {
            convert(xv, buf ^ 1, 0);
            prefetch(t + 1, 1, xv);
        }
        mma_step(2, xhb, whb);
        mma_step(3, xhb, whb);
        if (t + 1 < NT) convert(xv, buf ^ 1, 1);
        __syncthreads();
    }

    // ---- norms ----
    float* np = reinterpret_cast<float*>(smem + S_NP);
    float* ni = reinterpret_cast<float*>(smem + S_NI);
    np[half * 128 + cpx] = n2;
    __syncthreads();
    if (tid < 128)
        ni[tid] = 1.0f / fmaxf(sqrtf(np[tid] + np[128 + tid]), EPS);
    __syncthreads();

    // ---- epilogue ----
    float* ob = out + ((size_t)b * C) * HW + hw_base;
    #pragma unroll
    for (int m = 0; m < 2; m++) {
        int p0 = pxbase + m * 16 + r;
        int p1 = p0 + 8;
        float i0 = ni[p0], i1 = ni[p1];
        #pragma unroll
        for (int n = 0; n < 5; n++) {
            int ch = chbase + n * 8 + q * 2;
            ob[(size_t)ch * HW + p0]       = acc[m][n][0] * i0;
            ob[(size_t)(ch + 1) * HW + p0] = acc[m][n][1] * i0;
            ob[(size_t)ch * HW + p1]       = acc[m][n][2] * i1;
            ob[(size_t)(ch + 1) * HW + p1] = acc[m][n][3] * i1;
        }
    }
}

// ---------------------------------------------------------------------------
// Launch
// ---------------------------------------------------------------------------
extern "C" void kernel_launch(void* const* d_in, const int* in_sizes, int n_in,
                              void* d_out, int out_size) {
    const float* x   = (const float*)d_in[0];
    const float* w   = (const float*)d_in[1];
    const float* asf = (const float*)d_in[2];
    float* out = (float*)d_out;

    cudaFuncSetAttribute(coshead_main_kernel,
                         cudaFuncAttributeMaxDynamicSharedMemorySize, S_TOTAL);
    prep_weights_kernel<<<C, D>>>(w, asf);
    coshead_main_kernel<<<NPIX / PXT, NTHREADS, S_TOTAL>>>(x, out);
}

// round 14
// speedup vs baseline: 1.1321x; 1.1321x over previous
#include <cuda_runtime.h>
#include <cuda_bf16.h>
#include <cstdint>

#define B 8
#define D 256
#define HW (128 * 128)
#define C 80
#define NPIX (B * HW)
#define RANGE_EXTENDER 10.0f
#define EPS 1e-8f

#define KC 64                 // K per chunk
#define NT (D / KC)           // 4 chunks
#define PXT 128               // pixels per CTA (= M)
#define NTHREADS 256          // 8 warps: 4 px-groups x 2 ch-groups

// smem map (dynamic)
#define S_W   0               // 2 x 20480 (wh 10240 + wl 10240)
#define S_XS  40960           // 2 x (xh 16KB + xl 16KB)
#define S_NP  106496          // norm partials 2*128*4
#define S_NI  107520          // inv norms 128*4
#define S_TOTAL 108032

// Pre-split weight image, 16B-swizzled: [chunk t][hl][c][128B]
__device__ __align__(16) unsigned char g_wimg[NT * 2 * C * 128];

// ---------------------------------------------------------------------------
// helpers
// ---------------------------------------------------------------------------
__device__ __forceinline__ uint32_t smem_u32(const void* p) {
    return (uint32_t)__cvta_generic_to_shared(p);
}
__device__ __forceinline__ void cp_async16(uint32_t s, const void* g) {
    asm volatile("cp.async.cg.shared.global [%0], [%1], 16;" :: "r"(s), "l"(g) : "memory");
}
__device__ __forceinline__ void cp_commit() {
    asm volatile("cp.async.commit_group;" ::: "memory");
}
template <int N> __device__ __forceinline__ void cp_wait() {
    asm volatile("cp.async.wait_group %0;" :: "n"(N) : "memory");
}
__device__ __forceinline__ uint32_t cvt_bf16x2(float lo, float hi) {
    uint32_t r;
    asm("cvt.rn.bf16x2.f32 %0, %1, %2;" : "=r"(r) : "f"(hi), "f"(lo));
    return r;
}
__device__ __forceinline__ void ldsm_x4(uint32_t* r, uint32_t addr) {
    asm volatile("ldmatrix.sync.aligned.m8n8.x4.shared.b16 {%0,%1,%2,%3}, [%4];"
                 : "=r"(r[0]), "=r"(r[1]), "=r"(r[2]), "=r"(r[3]) : "r"(addr));
}
__device__ __forceinline__ void ldsm_x2(uint32_t* r, uint32_t addr) {
    asm volatile("ldmatrix.sync.aligned.m8n8.x2.shared.b16 {%0,%1}, [%2];"
                 : "=r"(r[0]), "=r"(r[1]) : "r"(addr));
}
__device__ __forceinline__ void mma_bf16(float* d, const uint32_t* a,
                                         uint32_t b0, uint32_t b1) {
    asm volatile(
        "mma.sync.aligned.m16n8k16.row.col.f32.bf16.bf16.f32 "
        "{%0,%1,%2,%3}, {%4,%5,%6,%7}, {%8,%9}, {%0,%1,%2,%3};"
        : "+f"(d[0]), "+f"(d[1]), "+f"(d[2]), "+f"(d[3])
        : "r"(a[0]), "r"(a[1]), "r"(a[2]), "r"(a[3]), "r"(b0), "r"(b1));
}

// ---------------------------------------------------------------------------
// Kernel 1: normalize+scale weights; bf16 hi/lo split; 16B-swizzled image
// rows of 128B, XOR on (row & 7): 8 consecutive rows -> 8 distinct chunks
// ---------------------------------------------------------------------------
__global__ void prep_weights_kernel(const float* __restrict__ w,
                                    const float* __restrict__ asf) {
    int c = blockIdx.x;
    int d = threadIdx.x;
    float v = w[c * D + d];

    __shared__ float red[D];
    red[d] = v * v;
    __syncthreads();
    #pragma unroll
    for (int s = D / 2; s > 0; s >>= 1) {
        if (d < s) red[d] += red[d + s];
        __syncthreads();
    }
    float scale = asf[c] * RANGE_EXTENDER / fmaxf(sqrtf(red[0]), EPS);
    float wn = v * scale;

    __nv_bfloat16 h = __float2bfloat16(wn);
    __nv_bfloat16 l = __float2bfloat16(wn - __bfloat162float(h));

    int t  = d >> 6;                  // chunk (KC=64)
    int kl = d & 63;
    int kp = kl >> 1;
    int ck = kp >> 2;                 // 16B chunk within 128B row (0..7)
    int word = kp & 3;
    int inner = ((ck ^ (c & 7)) << 4) + (word << 2) + (kl & 1) * 2;

    size_t hb = (size_t)t * 20480 + (size_t)c * 128 + inner;
    size_t lb = hb + 10240;
    *reinterpret_cast<__nv_bfloat16*>(g_wimg + hb) = h;
    *reinterpret_cast<__nv_bfloat16*>(g_wimg + lb) = l;
}

// ---------------------------------------------------------------------------
// Kernel 2: bf16 mma.sync GEMM, 3-term split, KC=64 chunks, convert woven
// between s-steps, conflict-free (row&7) swizzle.
// ---------------------------------------------------------------------------
__global__ __launch_bounds__(NTHREADS, 2)
void coshead_main_kernel(const float* __restrict__ x, float* __restrict__ out) {
    extern __shared__ char smem[];
    const uint32_t sb = smem_u32(smem);

    const int tid  = threadIdx.x;
    const int lane = tid & 31;
    const int wid  = tid >> 5;
    const int pxbase = (wid & 3) * 32;
    const int chbase = (wid >> 2) * 40;
    const int r = lane >> 2;
    const int q = lane & 3;
    const int mat = lane >> 3, rowi = lane & 7;

    const int tile    = blockIdx.x;
    const int b       = (tile * PXT) >> 14;
    const int hw_base = (tile * PXT) & (HW - 1);
    const float* xg = x + ((size_t)b * D) * HW + hw_base;

    const int cpx  = tid & 127;       // conversion pixel
    const int half = tid >> 7;        // conversion k-half of chunk (32 k each)
    float n2 = 0.0f;

    auto stage_w = [&](int t, int buf) {
        const unsigned char* ws = g_wimg + (size_t)t * 20480;
        uint32_t wd = sb + S_W + buf * 20480;
        #pragma unroll
        for (int i = tid, j = 0; j < 5; j++, i += NTHREADS)
            cp_async16(wd + i * 16, ws + i * 16);
        cp_commit();
    };

    // load 16 x values for (chunk t, this thread's half, batch) into regs
    auto prefetch = [&](int t, int batch, float* xv) {
        const float* xr = xg + (size_t)(t * KC + half * 32 + batch * 16) * HW + cpx;
        #pragma unroll
        for (int j = 0; j < 16; j++) xv[j] = xr[(size_t)j * HW];
    };

    // convert a 16-value batch into XS[buf]
    auto convert = [&](const float* xv, int buf, int batch) {
        char* xh = smem + S_XS + buf * 32768;
        char* xl = xh + 16384;
        int ck0 = (half * 32 + batch * 16) >> 3;   // first 16B chunk (2 per batch)
        #pragma unroll
        for (int c2 = 0; c2 < 2; c2++) {
            uint32_t wh[4], wl[4];
            #pragma unroll
            for (int i = 0; i < 4; i++) {
                float v0 = xv[c2 * 8 + i * 2];
                float v1 = xv[c2 * 8 + i * 2 + 1];
                n2 = fmaf(v0, v0, n2);
                n2 = fmaf(v1, v1, n2);
                __nv_bfloat16 h0 = __float2bfloat16(v0);
                __nv_bfloat16 h1 = __float2bfloat16(v1);
                float l0 = v0 - __bfloat162float(h0);
                float l1 = v1 - __bfloat162float(h1);
                wh[i] = ((uint32_t)__bfloat16_as_ushort(h1) << 16)
                      | __bfloat16_as_ushort(h0);
                wl[i] = cvt_bf16x2(l0, l1);
            }
            int ck = ck0 + c2;
            int addr = cpx * 128 + ((ck ^ (cpx & 7)) << 4);
            *reinterpret_cast<uint4*>(xh + addr) = make_uint4(wh[0], wh[1], wh[2], wh[3]);
            *reinterpret_cast<uint4*>(xl + addr) = make_uint4(wl[0], wl[1], wl[2], wl[3]);
        }
    };

    float acc[2][5][4];
    #pragma unroll
    for (int m = 0; m < 2; m++)
        #pragma unroll
        for (int n = 0; n < 5; n++)
            #pragma unroll
            for (int k = 0; k < 4; k++) acc[m][n][k] = 0.0f;

    // one k16-step of MMAs (s in 0..3)
    auto mma_step = [&](int s, uint32_t xhb, uint32_t whb) {
        uint32_t ah[2][4], al_[2][4];
        #pragma unroll
        for (int m = 0; m < 2; m++) {
            int px = pxbase + m * 16 + ((mat & 1) << 3) + rowi;
            int ck = 2 * s + (mat >> 1);
            uint32_t a = xhb + px * 128 + ((ck ^ (px & 7)) << 4);
            ldsm_x4(ah[m], a);
            ldsm_x4(al_[m], a + 16384);
        }
        uint32_t bh[5][2], bl[5][2];
        #pragma unroll
        for (int u = 0; u < 2; u++) {
            int cc = chbase + u * 16 + ((mat >> 1) << 3) + rowi;
            int ck = 2 * s + (mat & 1);
            uint32_t a = whb + cc * 128 + ((ck ^ (cc & 7)) << 4);
            uint32_t rr[4];
            ldsm_x4(rr, a);
            bh[2 * u][0] = rr[0]; bh[2 * u][1] = rr[1];
            bh[2 * u + 1][0] = rr[2]; bh[2 * u + 1][1] = rr[3];
            ldsm_x4(rr, a + 10240);
            bl[2 * u][0] = rr[0]; bl[2 * u][1] = rr[1];
            bl[2 * u + 1][0] = rr[2]; bl[2 * u + 1][1] = rr[3];
        }
        {
            int cc = chbase + 32 + rowi;
            int ck = 2 * s + (mat & 1);
            uint32_t a = whb + cc * 128 + ((ck ^ (cc & 7)) << 4);
            uint32_t rr[2];
            ldsm_x2(rr, a);
            bh[4][0] = rr[0]; bh[4][1] = rr[1];
            ldsm_x2(rr, a + 10240);
            bl[4][0] = rr[0]; bl[4][1] = rr[1];
        }
        #pragma unroll
        for (int n = 0; n < 5; n++)
            #pragma unroll
            for (int m = 0; m < 2; m++) {
                mma_bf16(acc[m][n], ah[m],  bh[n][0], bh[n][1]);
                mma_bf16(acc[m][n], al_[m], bh[n][0], bh[n][1]);
                mma_bf16(acc[m][n], ah[m],  bl[n][0], bl[n][1]);
            }
    };

    // ---- prologue ----
    stage_w(0, 0);
    {
        float xv[16];
        prefetch(0, 0, xv);
        convert(xv, 0, 0);
        prefetch(0, 1, xv);
        convert(xv, 0, 1);
    }
    cp_wait<0>();
    __syncthreads();

    for (int t = 0; t < NT; t++) {
        const int buf = t & 1;
        if (t + 1 < NT) { stage_w(t + 1, buf ^ 1); cp_wait<1>(); }
        else           { cp_wait<0>(); }
        if (t > 0) __syncthreads();   // XS[buf] converted; W[buf] visible

        const uint32_t xhb = sb + S_XS + buf * 32768;
        const uint32_t whb = sb + S_W + buf * 20480;

        float xv[16];
        if (t + 1 < NT) prefetch(t + 1, 0, xv);
        mma_step(0, xhb, whb);
        mma_step(1, xhb, whb);
        if (t + 1 < NT) {
            convert(xv, buf ^ 1, 0);
            prefetch(t + 1, 1, xv);
        }
        mma_step(2, xhb, whb);
        mma_step(3, xhb, whb);
        if (t + 1 < NT) convert(xv, buf ^ 1, 1);
        __syncthreads();
    }

    // ---- norms ----
    float* np = reinterpret_cast<float*>(smem + S_NP);
    float* ni = reinterpret_cast<float*>(smem + S_NI);
    np[half * 128 + cpx] = n2;
    __syncthreads();
    if (tid < 128)
        ni[tid] = 1.0f / fmaxf(sqrtf(np[tid] + np[128 + tid]), EPS);
    __syncthreads();

    // ---- epilogue ----
    float* ob = out + ((size_t)b * C) * HW + hw_base;
    #pragma unroll
    for (int m = 0; m < 2; m++) {
        int p0 = pxbase + m * 16 + r;
        int p1 = p0 + 8;
        float i0 = ni[p0], i1 = ni[p1];
        #pragma unroll
        for (int n = 0; n < 5; n++) {
            int ch = chbase + n * 8 + q * 2;
            ob[(size_t)ch * HW + p0]       = acc[m][n][0] * i0;
            ob[(size_t)(ch + 1) * HW + p0] = acc[m][n][1] * i0;
            ob[(size_t)ch * HW + p1]       = acc[m][n][2] * i1;
            ob[(size_t)(ch + 1) * HW + p1] = acc[m][n][3] * i1;
        }
    }
}

// ---------------------------------------------------------------------------
// Launch
// ---------------------------------------------------------------------------
extern "C" void kernel_launch(void* const* d_in, const int* in_sizes, int n_in,
                              void* d_out, int out_size) {
    const float* x   = (const float*)d_in[0];
    const float* w   = (const float*)d_in[1];
    const float* asf = (const float*)d_in[2];
    float* out = (float*)d_out;

    cudaFuncSetAttribute(coshead_main_kernel,
                         cudaFuncAttributeMaxDynamicSharedMemorySize, S_TOTAL);
    prep_weights_kernel<<<C, D>>>(w, asf);
    coshead_main_kernel<<<NPIX / PXT, NTHREADS, S_TOTAL>>>(x, out);
}

// round 15
// speedup vs baseline: 1.2517x; 1.1056x over previous
#include <cuda_runtime.h>
#include <cuda_fp16.h>
#include <cstdint>

#define B 8
#define D 256
#define HW (128 * 128)
#define C 80
#define NPIX (B * HW)
#define RANGE_EXTENDER 10.0f
#define EPS 1e-8f

#define KC 32                 // K per chunk
#define NT (D / KC)           // 8 chunks
#define PXT 128               // pixels per CTA (= M)
#define NTHREADS 256          // 8 warps: 4 px-groups x 2 ch-groups

// smem map (dynamic)
#define S_XS 0                // swizzled fp16 x: 2 x (xh 8KB + xl 8KB)
#define S_W  32768            // w image: 2 x 5120 (fp16, single)
#define S_NP 43008            // norm partials 2*128*4
#define S_NI 44032            // inv norms 128*4
#define S_TOTAL 44544

// fp16 weight image, 16B-swizzled: [chunk t][c][64B]
__device__ __align__(16) unsigned char g_wimg[NT * C * 64];

// ---------------------------------------------------------------------------
// helpers
// ---------------------------------------------------------------------------
__device__ __forceinline__ uint32_t smem_u32(const void* p) {
    return (uint32_t)__cvta_generic_to_shared(p);
}
__device__ __forceinline__ void cp_async16(uint32_t s, const void* g) {
    asm volatile("cp.async.cg.shared.global [%0], [%1], 16;" :: "r"(s), "l"(g) : "memory");
}
__device__ __forceinline__ void cp_commit() {
    asm volatile("cp.async.commit_group;" ::: "memory");
}
template <int N> __device__ __forceinline__ void cp_wait() {
    asm volatile("cp.async.wait_group %0;" :: "n"(N) : "memory");
}
__device__ __forceinline__ void ldsm_x4(uint32_t* r, uint32_t addr) {
    asm volatile("ldmatrix.sync.aligned.m8n8.x4.shared.b16 {%0,%1,%2,%3}, [%4];"
                 : "=r"(r[0]), "=r"(r[1]), "=r"(r[2]), "=r"(r[3]) : "r"(addr));
}
__device__ __forceinline__ void ldsm_x2(uint32_t* r, uint32_t addr) {
    asm volatile("ldmatrix.sync.aligned.m8n8.x2.shared.b16 {%0,%1}, [%2];"
                 : "=r"(r[0]), "=r"(r[1]) : "r"(addr));
}
__device__ __forceinline__ void mma_f16(float* d, const uint32_t* a,
                                        uint32_t b0, uint32_t b1) {
    asm volatile(
        "mma.sync.aligned.m16n8k16.row.col.f32.f16.f16.f32 "
        "{%0,%1,%2,%3}, {%4,%5,%6,%7}, {%8,%9}, {%0,%1,%2,%3};"
        : "+f"(d[0]), "+f"(d[1]), "+f"(d[2]), "+f"(d[3])
        : "r"(a[0]), "r"(a[1]), "r"(a[2]), "r"(a[3]), "r"(b0), "r"(b1));
}

// ---------------------------------------------------------------------------
// Kernel 1: normalize+scale weights; single fp16; 16B-swizzled image
// (same 64B-row swizzle as R10 — verified conflict-free for ldsm/STS phases)
// ---------------------------------------------------------------------------
__global__ void prep_weights_kernel(const float* __restrict__ w,
                                    const float* __restrict__ asf) {
    int c = blockIdx.x;
    int d = threadIdx.x;
    float v = w[c * D + d];

    __shared__ float red[D];
    red[d] = v * v;
    __syncthreads();
    #pragma unroll
    for (int s = D / 2; s > 0; s >>= 1) {
        if (d < s) red[d] += red[d + s];
        __syncthreads();
    }
    float scale = asf[c] * RANGE_EXTENDER / fmaxf(sqrtf(red[0]), EPS);
    __half h = __float2half_rn(v * scale);

    int t  = d >> 5;
    int kl = d & 31;
    int kp = kl >> 1;
    int chunk = kp >> 2;
    int word  = kp & 3;
    int inner = ((chunk ^ ((c >> 1) & 3)) << 4) + (word << 2) + (kl & 1) * 2;

    size_t hb = ((size_t)t * C + c) * 64 + inner;
    *reinterpret_cast<__half*>(g_wimg + hb) = h;
}

// ---------------------------------------------------------------------------
// Kernel 2: fp16 mma.sync GEMM, 2-term x-split (xh+xl fp16), single-fp16 w.
// R10 structure: per-chunk w staging, gmem->reg x prefetch under MMAs.
// ---------------------------------------------------------------------------
__global__ __launch_bounds__(NTHREADS, 2)
void coshead_main_kernel(const float* __restrict__ x, float* __restrict__ out) {
    extern __shared__ char smem[];
    const uint32_t sb = smem_u32(smem);

    const int tid  = threadIdx.x;
    const int lane = tid & 31;
    const int wid  = tid >> 5;
    const int pxbase = (wid & 3) * 32;
    const int chbase = (wid >> 2) * 40;
    const int r = lane >> 2;
    const int q = lane & 3;
    const int mat = lane >> 3, rowi = lane & 7;

    const int tile    = blockIdx.x;
    const int b       = (tile * PXT) >> 14;
    const int hw_base = (tile * PXT) & (HW - 1);
    const float* xg = x + ((size_t)b * D) * HW + hw_base;

    const int cpx  = tid & 127;      // conversion pixel
    const int half = tid >> 7;       // conversion k-half
    float n2 = 0.0f;

    auto stage_w = [&](int t, int buf) {
        const unsigned char* ws = g_wimg + (size_t)t * 5120;
        uint32_t wd = sb + S_W + buf * 5120;
        #pragma unroll
        for (int i = tid, j = 0; j < 2; j++, i += NTHREADS)
            if (i < 320) cp_async16(wd + i * 16, ws + i * 16);
        cp_commit();
    };

    // convert 16 x values (this thread's half of a chunk) into XS[buf]
    auto convert = [&](const float* xv, int buf) {
        char* xh = smem + S_XS + buf * 16384;
        char* xl = xh + 8192;
        #pragma unroll
        for (int c2 = 0; c2 < 2; c2++) {
            int chunk = half * 2 + c2;
            uint32_t wh[4], wl[4];
            #pragma unroll
            for (int i = 0; i < 4; i++) {
                float v0 = xv[c2 * 8 + i * 2];
                float v1 = xv[c2 * 8 + i * 2 + 1];
                n2 = fmaf(v0, v0, n2);
                n2 = fmaf(v1, v1, n2);
                __half h0 = __float2half_rn(v0);
                __half h1 = __float2half_rn(v1);
                __half l0 = __float2half_rn(v0 - __half2float(h0));
                __half l1 = __float2half_rn(v1 - __half2float(h1));
                wh[i] = ((uint32_t)__half_as_ushort(h1) << 16)
                      | __half_as_ushort(h0);
                wl[i] = ((uint32_t)__half_as_ushort(l1) << 16)
                      | __half_as_ushort(l0);
            }
            int addr = cpx * 64 + ((chunk ^ ((cpx >> 1) & 3)) << 4);
            *reinterpret_cast<uint4*>(xh + addr) = make_uint4(wh[0], wh[1], wh[2], wh[3]);
            *reinterpret_cast<uint4*>(xl + addr) = make_uint4(wl[0], wl[1], wl[2], wl[3]);
        }
    };

    float acc[2][5][4];
    #pragma unroll
    for (int m = 0; m < 2; m++)
        #pragma unroll
        for (int n = 0; n < 5; n++)
            #pragma unroll
            for (int k = 0; k < 4; k++) acc[m][n][k] = 0.0f;

    // prologue
    stage_w(0, 0);
    {
        float xv[16];
        const float* xr = xg + (size_t)(half * 16) * HW + cpx;
        #pragma unroll
        for (int j = 0; j < 16; j++) xv[j] = xr[(size_t)j * HW];
        convert(xv, 0);
    }
    cp_wait<0>();
    __syncthreads();

    for (int t = 0; t < NT; t++) {
        const int buf = t & 1;
        if (t + 1 < NT) { stage_w(t + 1, buf ^ 1); cp_wait<1>(); }
        else           { cp_wait<0>(); }
        if (t > 0) __syncthreads();

        // prefetch next chunk's x into registers (drains under the MMAs)
        float xv[16];
        if (t + 1 < NT) {
            const float* xr = xg + (size_t)((t + 1) * KC + half * 16) * HW + cpx;
            #pragma unroll
            for (int j = 0; j < 16; j++) xv[j] = xr[(size_t)j * HW];
        }

        const uint32_t xhb = sb + S_XS + buf * 16384;
        const uint32_t whb = sb + S_W + buf * 5120;

        #pragma unroll
        for (int s = 0; s < 2; s++) {
            uint32_t ah[2][4], al_[2][4];
            #pragma unroll
            for (int m = 0; m < 2; m++) {
                int px = pxbase + m * 16 + ((mat & 1) << 3) + rowi;
                int ck = 2 * s + (mat >> 1);
                uint32_t a = xhb + px * 64 + ((ck ^ ((px >> 1) & 3)) << 4);
                ldsm_x4(ah[m], a);
                ldsm_x4(al_[m], a + 8192);
            }
            uint32_t bh[5][2];
            #pragma unroll
            for (int u = 0; u < 2; u++) {
                int cc = chbase + u * 16 + ((mat >> 1) << 3) + rowi;
                int ck = 2 * s + (mat & 1);
                uint32_t a = whb + cc * 64 + ((ck ^ ((cc >> 1) & 3)) << 4);
                uint32_t rr[4];
                ldsm_x4(rr, a);
                bh[2 * u][0] = rr[0]; bh[2 * u][1] = rr[1];
                bh[2 * u + 1][0] = rr[2]; bh[2 * u + 1][1] = rr[3];
            }
            {
                int cc = chbase + 32 + rowi;
                int ck = 2 * s + (mat & 1);
                uint32_t a = whb + cc * 64 + ((ck ^ ((cc >> 1) & 3)) << 4);
                uint32_t rr[2];
                ldsm_x2(rr, a);
                bh[4][0] = rr[0]; bh[4][1] = rr[1];
            }
            #pragma unroll
            for (int n = 0; n < 5; n++)
                #pragma unroll
                for (int m = 0; m < 2; m++) {
                    mma_f16(acc[m][n], ah[m],  bh[n][0], bh[n][1]);
                    mma_f16(acc[m][n], al_[m], bh[n][0], bh[n][1]);
                }
        }

        if (t + 1 < NT) convert(xv, buf ^ 1);
        __syncthreads();
    }

    // ---- norms ----
    float* np = reinterpret_cast<float*>(smem + S_NP);
    float* ni = reinterpret_cast<float*>(smem + S_NI);
    np[half * 128 + cpx] = n2;
    __syncthreads();
    if (tid < 128)
        ni[tid] = 1.0f / fmaxf(sqrtf(np[tid] + np[128 + tid]), EPS);
    __syncthreads();

    // ---- epilogue ----
    float* ob = out + ((size_t)b * C) * HW + hw_base;
    #pragma unroll
    for (int m = 0; m < 2; m++) {
        int p0 = pxbase + m * 16 + r;
        int p1 = p0 + 8;
        float i0 = ni[p0], i1 = ni[p1];
        #pragma unroll
        for (int n = 0; n < 5; n++) {
            int ch = chbase + n * 8 + q * 2;
            ob[(size_t)ch * HW + p0]       = acc[m][n][0] * i0;
            ob[(size_t)(ch + 1) * HW + p0] = acc[m][n][1] * i0;
            ob[(size_t)ch * HW + p1]       = acc[m][n][2] * i1;
            ob[(size_t)(ch + 1) * HW + p1] = acc[m][n][3] * i1;
        }
    }
}

// ---------------------------------------------------------------------------
// Launch
// ---------------------------------------------------------------------------
extern "C" void kernel_launch(void* const* d_in, const int* in_sizes, int n_in,
                              void* d_out, int out_size) {
    const float* x   = (const float*)d_in[0];
    const float* w   = (const float*)d_in[1];
    const float* asf = (const float*)d_in[2];
    float* out = (float*)d_out;

    cudaFuncSetAttribute(coshead_main_kernel,
                         cudaFuncAttributeMaxDynamicSharedMemorySize, S_TOTAL);
    prep_weights_kernel<<<C, D>>>(w, asf);
    coshead_main_kernel<<<NPIX / PXT, NTHREADS, S_TOTAL>>>(x, out);
}

// round 16
// speedup vs baseline: 1.4591x; 1.1657x over previous
#include <cuda_runtime.h>
#include <cuda_fp16.h>
#include <cstdint>

#define B 8
#define D 256
#define HW (128 * 128)
#define C 80
#define NPIX (B * HW)
#define RANGE_EXTENDER 10.0f
#define EPS 1e-8f

#define KC 32                 // K per chunk
#define NT (D / KC)           // 8 chunks
#define PXT 64                // pixels per CTA (= M)
#define NTHREADS 128          // 4 warps: 2 px-groups x 2 ch-groups

// smem map (dynamic)
#define S_XS 0                // swizzled fp16 x: 2 x (xh 4KB + xl 4KB)
#define S_W  16384            // w image: 2 x 5120 (fp16)
#define S_NP 26624            // norm partials 2*64*4
#define S_NI 27136            // inv norms 64*4
#define S_TOTAL 27392

// fp16 weight image, 16B-swizzled: [chunk t][c][64B]
__device__ __align__(16) unsigned char g_wimg[NT * C * 64];

// ---------------------------------------------------------------------------
// helpers
// ---------------------------------------------------------------------------
__device__ __forceinline__ uint32_t smem_u32(const void* p) {
    return (uint32_t)__cvta_generic_to_shared(p);
}
__device__ __forceinline__ void cp_async16(uint32_t s, const void* g) {
    asm volatile("cp.async.cg.shared.global [%0], [%1], 16;" :: "r"(s), "l"(g) : "memory");
}
__device__ __forceinline__ void cp_commit() {
    asm volatile("cp.async.commit_group;" ::: "memory");
}
template <int N> __device__ __forceinline__ void cp_wait() {
    asm volatile("cp.async.wait_group %0;" :: "n"(N) : "memory");
}
__device__ __forceinline__ void ldsm_x4(uint32_t* r, uint32_t addr) {
    asm volatile("ldmatrix.sync.aligned.m8n8.x4.shared.b16 {%0,%1,%2,%3}, [%4];"
                 : "=r"(r[0]), "=r"(r[1]), "=r"(r[2]), "=r"(r[3]) : "r"(addr));
}
__device__ __forceinline__ void ldsm_x2(uint32_t* r, uint32_t addr) {
    asm volatile("ldmatrix.sync.aligned.m8n8.x2.shared.b16 {%0,%1}, [%2];"
                 : "=r"(r[0]), "=r"(r[1]) : "r"(addr));
}
__device__ __forceinline__ void mma_f16(float* d, const uint32_t* a,
                                        uint32_t b0, uint32_t b1) {
    asm volatile(
        "mma.sync.aligned.m16n8k16.row.col.f32.f16.f16.f32 "
        "{%0,%1,%2,%3}, {%4,%5,%6,%7}, {%8,%9}, {%0,%1,%2,%3};"
        : "+f"(d[0]), "+f"(d[1]), "+f"(d[2]), "+f"(d[3])
        : "r"(a[0]), "r"(a[1]), "r"(a[2]), "r"(a[3]), "r"(b0), "r"(b1));
}

// ---------------------------------------------------------------------------
// Kernel 1: normalize+scale weights; single fp16; 16B-swizzled image
// ---------------------------------------------------------------------------
__global__ void prep_weights_kernel(const float* __restrict__ w,
                                    const float* __restrict__ asf) {
    int c = blockIdx.x;
    int d = threadIdx.x;
    float v = w[c * D + d];

    __shared__ float red[D];
    red[d] = v * v;
    __syncthreads();
    #pragma unroll
    for (int s = D / 2; s > 0; s >>= 1) {
        if (d < s) red[d] += red[d + s];
        __syncthreads();
    }
    float scale = asf[c] * RANGE_EXTENDER / fmaxf(sqrtf(red[0]), EPS);
    __half h = __float2half_rn(v * scale);

    int t  = d >> 5;
    int kl = d & 31;
    int kp = kl >> 1;
    int chunk = kp >> 2;
    int word  = kp & 3;
    int inner = ((chunk ^ ((c >> 1) & 3)) << 4) + (word << 2) + (kl & 1) * 2;

    size_t hb = ((size_t)t * C + c) * 64 + inner;
    *reinterpret_cast<__half*>(g_wimg + hb) = h;
}

// ---------------------------------------------------------------------------
// Kernel 2: fp16 mma.sync GEMM, 2-term x-split, 128-thread CTAs (4 warps),
// 4 independent CTAs/SM to break phase lockstep.
// ---------------------------------------------------------------------------
__global__ __launch_bounds__(NTHREADS, 4)
void coshead_main_kernel(const float* __restrict__ x, float* __restrict__ out) {
    extern __shared__ char smem[];
    const uint32_t sb = smem_u32(smem);

    const int tid  = threadIdx.x;
    const int lane = tid & 31;
    const int wid  = tid >> 5;
    const int pxbase = (wid & 1) * 32;
    const int chbase = (wid >> 1) * 40;
    const int r = lane >> 2;
    const int q = lane & 3;
    const int mat = lane >> 3, rowi = lane & 7;

    const int tile    = blockIdx.x;
    const int b       = (tile * PXT) >> 14;
    const int hw_base = (tile * PXT) & (HW - 1);
    const float* xg = x + ((size_t)b * D) * HW + hw_base;

    const int cpx  = tid & 63;       // conversion pixel (0..63)
    const int half = tid >> 6;       // conversion k-half (16 k each)
    float n2 = 0.0f;

    auto stage_w = [&](int t, int buf) {
        const unsigned char* ws = g_wimg + (size_t)t * 5120;
        uint32_t wd = sb + S_W + buf * 5120;
        #pragma unroll
        for (int i = tid, j = 0; j < 3; j++, i += NTHREADS)
            if (i < 320) cp_async16(wd + i * 16, ws + i * 16);
        cp_commit();
    };

    // convert 16 x values (this thread's half of a chunk) into XS[buf]
    auto convert = [&](const float* xv, int buf) {
        char* xh = smem + S_XS + buf * 8192;
        char* xl = xh + 4096;
        #pragma unroll
        for (int c2 = 0; c2 < 2; c2++) {
            int chunk = half * 2 + c2;
            uint32_t wh[4], wl[4];
            #pragma unroll
            for (int i = 0; i < 4; i++) {
                float v0 = xv[c2 * 8 + i * 2];
                float v1 = xv[c2 * 8 + i * 2 + 1];
                n2 = fmaf(v0, v0, n2);
                n2 = fmaf(v1, v1, n2);
                __half2 h2 = __float22half2_rn(make_float2(v0, v1));
                float2 hf = __half22float2(h2);
                __half2 l2 = __float22half2_rn(make_float2(v0 - hf.x, v1 - hf.y));
                wh[i] = *reinterpret_cast<uint32_t*>(&h2);
                wl[i] = *reinterpret_cast<uint32_t*>(&l2);
            }
            int addr = cpx * 64 + ((chunk ^ ((cpx >> 1) & 3)) << 4);
            *reinterpret_cast<uint4*>(xh + addr) = make_uint4(wh[0], wh[1], wh[2], wh[3]);
            *reinterpret_cast<uint4*>(xl + addr) = make_uint4(wl[0], wl[1], wl[2], wl[3]);
        }
    };

    float acc[2][5][4];
    #pragma unroll
    for (int m = 0; m < 2; m++)
        #pragma unroll
        for (int n = 0; n < 5; n++)
            #pragma unroll
            for (int k = 0; k < 4; k++) acc[m][n][k] = 0.0f;

    // prologue
    stage_w(0, 0);
    {
        float xv[16];
        const float* xr = xg + (size_t)(half * 16) * HW + cpx;
        #pragma unroll
        for (int j = 0; j < 16; j++) xv[j] = xr[(size_t)j * HW];
        convert(xv, 0);
    }
    cp_wait<0>();
    __syncthreads();

    for (int t = 0; t < NT; t++) {
        const int buf = t & 1;
        if (t + 1 < NT) { stage_w(t + 1, buf ^ 1); cp_wait<1>(); }
        else           { cp_wait<0>(); }
        if (t > 0) __syncthreads();

        // prefetch next chunk's x into registers (drains under the MMAs)
        float xv[16];
        if (t + 1 < NT) {
            const float* xr = xg + (size_t)((t + 1) * KC + half * 16) * HW + cpx;
            #pragma unroll
            for (int j = 0; j < 16; j++) xv[j] = xr[(size_t)j * HW];
        }

        const uint32_t xhb = sb + S_XS + buf * 8192;
        const uint32_t whb = sb + S_W + buf * 5120;

        #pragma unroll
        for (int s = 0; s < 2; s++) {
            uint32_t ah[2][4], al_[2][4];
            #pragma unroll
            for (int m = 0; m < 2; m++) {
                int px = pxbase + m * 16 + ((mat & 1) << 3) + rowi;
                int ck = 2 * s + (mat >> 1);
                uint32_t a = xhb + px * 64 + ((ck ^ ((px >> 1) & 3)) << 4);
                ldsm_x4(ah[m], a);
                ldsm_x4(al_[m], a + 4096);
            }
            uint32_t bh[5][2];
            #pragma unroll
            for (int u = 0; u < 2; u++) {
                int cc = chbase + u * 16 + ((mat >> 1) << 3) + rowi;
                int ck = 2 * s + (mat & 1);
                uint32_t a = whb + cc * 64 + ((ck ^ ((cc >> 1) & 3)) << 4);
                uint32_t rr[4];
                ldsm_x4(rr, a);
                bh[2 * u][0] = rr[0]; bh[2 * u][1] = rr[1];
                bh[2 * u + 1][0] = rr[2]; bh[2 * u + 1][1] = rr[3];
            }
            {
                int cc = chbase + 32 + rowi;
                int ck = 2 * s + (mat & 1);
                uint32_t a = whb + cc * 64 + ((ck ^ ((cc >> 1) & 3)) << 4);
                uint32_t rr[2];
                ldsm_x2(rr, a);
                bh[4][0] = rr[0]; bh[4][1] = rr[1];
            }
            #pragma unroll
            for (int n = 0; n < 5; n++)
                #pragma unroll
                for (int m = 0; m < 2; m++) {
                    mma_f16(acc[m][n], ah[m],  bh[n][0], bh[n][1]);
                    mma_f16(acc[m][n], al_[m], bh[n][0], bh[n][1]);
                }
        }

        if (t + 1 < NT) convert(xv, buf ^ 1);
        __syncthreads();
    }

    // ---- norms ----
    float* np = reinterpret_cast<float*>(smem + S_NP);
    float* ni = reinterpret_cast<float*>(smem + S_NI);
    np[half * 64 + cpx] = n2;
    __syncthreads();
    if (tid < 64)
        ni[tid] = 1.0f / fmaxf(sqrtf(np[tid] + np[64 + tid]), EPS);
    __syncthreads();

    // ---- epilogue ----
    float* ob = out + ((size_t)b * C) * HW + hw_base;
    #pragma unroll
    for (int m = 0; m < 2; m++) {
        int p0 = pxbase + m * 16 + r;
        int p1 = p0 + 8;
        float i0 = ni[p0], i1 = ni[p1];
        #pragma unroll
        for (int n = 0; n < 5; n++) {
            int ch = chbase + n * 8 + q * 2;
            ob[(size_t)ch * HW + p0]       = acc[m][n][0] * i0;
            ob[(size_t)(ch + 1) * HW + p0] = acc[m][n][1] * i0;
            ob[(size_t)ch * HW + p1]       = acc[m][n][2] * i1;
            ob[(size_t)(ch + 1) * HW + p1] = acc[m][n][3] * i1;
        }
    }
}

// ---------------------------------------------------------------------------
// Launch
// ---------------------------------------------------------------------------
extern "C" void kernel_launch(void* const* d_in, const int* in_sizes, int n_in,
                              void* d_out, int out_size) {
    const float* x   = (const float*)d_in[0];
    const float* w   = (const float*)d_in[1];
    const float* asf = (const float*)d_in[2];
    float* out = (float*)d_out;

    cudaFuncSetAttribute(coshead_main_kernel,
                         cudaFuncAttributeMaxDynamicSharedMemorySize, S_TOTAL);
    prep_weights_kernel<<<C, D>>>(w, asf);
    coshead_main_kernel<<<NPIX / PXT, NTHREADS, S_TOTAL>>>(x, out);
}